// round 17
// baseline (speedup 1.0000x reference)
#include <cuda_runtime.h>
#include <cuda_fp16.h>
#include <cstdint>

#define Bn 4
#define Tn 512
#define Dn 1024
#define Hn 16
#define HSn 64
#define Ln 8
#define Vn 32000
#define Mn (Bn*Tn)       // 2048
#define FFn (4*Dn)       // 4096
#define BHn (Bn*Hn)      // 64

// ---------------- fp32 scratch ----------------
__device__ float g_h[Mn*Dn];

// ---------------- fp16 planes ----------------
__device__ __half g_yS[Mn*Dn];
__device__ __half g_qS[Mn*Dn];                    // pre-scaled by 1/8
__device__ __half g_kS[Mn*Dn];
__device__ __half g_vS[Mn*Dn];                    // natural [t, d] layout
__device__ __half g_oS[Mn*Dn];
__device__ __half g_aS[Mn*FFn];

// ---------------- fp16 weights (NATIVE [K,N] row-major, single plane) ------
__device__ __half g_wqkvS[(size_t)Ln*3*Dn*Dn];   // [1024, 3072] per layer
__device__ __half g_woS[Ln*Dn*Dn];               // [1024, 1024]
__device__ __half g_w1S[Ln*Dn*FFn];              // [1024, 4096]
__device__ __half g_w2S[Ln*Dn*FFn];              // [4096, 1024]
__device__ __half g_wfS[(size_t)Dn*Vn];          // [1024, 32000]

// ==================== helpers ====================
__device__ __forceinline__ uint32_t smem_u32(const void* p){
    uint32_t a;
    asm("{ .reg .u64 t; cvta.to.shared.u64 t, %1; cvt.u32.u64 %0, t; }" : "=r"(a) : "l"(p));
    return a;
}
#define CP16(dst, src) \
    asm volatile("cp.async.cg.shared.global [%0], [%1], 16;" :: "r"(dst), "l"(src))
#define CP_COMMIT() asm volatile("cp.async.commit_group;" ::: "memory")
#define CP_WAIT1() asm volatile("cp.async.wait_group 1;" ::: "memory")
#define CP_WAIT0() asm volatile("cp.async.wait_group 0;" ::: "memory")

#define LDSM4(r0,r1,r2,r3,addr) \
    asm volatile("ldmatrix.sync.aligned.m8n8.x4.shared.b16 {%0,%1,%2,%3}, [%4];" \
        : "=r"(r0),"=r"(r1),"=r"(r2),"=r"(r3) : "r"(addr))
#define LDSM4T(r0,r1,r2,r3,addr) \
    asm volatile("ldmatrix.sync.aligned.m8n8.x4.trans.shared.b16 {%0,%1,%2,%3}, [%4];" \
        : "=r"(r0),"=r"(r1),"=r"(r2),"=r"(r3) : "r"(addr))

#define MMA16816(d, a, b) \
    asm volatile("mma.sync.aligned.m16n8k16.row.col.f32.f16.f16.f32 " \
        "{%0,%1,%2,%3}, {%4,%5,%6,%7}, {%8,%9}, {%0,%1,%2,%3};" \
        : "+f"((d)[0]),"+f"((d)[1]),"+f"((d)[2]),"+f"((d)[3]) \
        : "r"((a)[0]),"r"((a)[1]),"r"((a)[2]),"r"((a)[3]), "r"((b)[0]),"r"((b)[1]))

// ==================== reductions ====================
__device__ __forceinline__ float warpSum(float v){
#pragma unroll
    for (int o = 16; o > 0; o >>= 1) v += __shfl_down_sync(0xffffffffu, v, o);
    return v;
}
__device__ __forceinline__ float blockSum(float v, float* sh){
    int lane = threadIdx.x & 31, w = threadIdx.x >> 5;
    v = warpSum(v);
    __syncthreads();
    if (lane == 0) sh[w] = v;
    __syncthreads();
    int nw = blockDim.x >> 5;
    v = (threadIdx.x < (unsigned)nw) ? sh[threadIdx.x] : 0.f;
    if (w == 0) v = warpSum(v);
    if (threadIdx.x == 0) sh[0] = v;
    __syncthreads();
    return sh[0];
}

// ==================== small kernels ====================
__global__ void embed_k(const int* __restrict__ x, const float* __restrict__ ce,
                        const float* __restrict__ pe){
    int idx = blockIdx.x * blockDim.x + threadIdx.x;
    int d  = idx & (Dn - 1);
    int mt = idx >> 10;
    int t  = mt & (Tn - 1);
    g_h[idx] = ce[(size_t)x[mt] * Dn + d] + pe[t * Dn + d];
}

// LayerNorm fused with single fp16 plane output
__global__ __launch_bounds__(256) void ln_k(const float* __restrict__ in,
                                            __half* __restrict__ outH,
                                            const float* __restrict__ gs,
                                            const float* __restrict__ gb){
    __shared__ float sh[32];
    int row = blockIdx.x;
    const float4* xr = (const float4*)(in + (size_t)row * Dn);
    float4 vv = xr[threadIdx.x];
    float s  = vv.x + vv.y + vv.z + vv.w;
    float sq = vv.x*vv.x + vv.y*vv.y + vv.z*vv.z + vv.w*vv.w;
    s  = blockSum(s, sh);
    sq = blockSum(sq, sh);
    float mean = s * (1.f / Dn);
    float var  = sq * (1.f / Dn) - mean * mean;
    float r = rsqrtf(var + 1e-5f);
    int i0 = threadIdx.x * 4;
    float o[4];
    o[0] = (vv.x - mean) * r * gs[i0+0] + gb[i0+0];
    o[1] = (vv.y - mean) * r * gs[i0+1] + gb[i0+1];
    o[2] = (vv.z - mean) * r * gs[i0+2] + gb[i0+2];
    o[3] = (vv.w - mean) * r * gs[i0+3] + gb[i0+3];
    __half2 h2[2];
    h2[0] = __half2(__float2half_rn(o[0]), __float2half_rn(o[1]));
    h2[1] = __half2(__float2half_rn(o[2]), __float2half_rn(o[3]));
    *(uint2*)(outH + (size_t)row * Dn + i0) = *(uint2*)h2;
}

// flat fp32 -> fp16 convert, 16 elems/thread (4 independent float4 loads)
__global__ __launch_bounds__(256) void convF_k(const float* __restrict__ in,
                                               __half* __restrict__ out, int n16){
    int idx = blockIdx.x * blockDim.x + threadIdx.x;
    if (idx >= n16) return;
    const float4* src = (const float4*)in + (size_t)idx * 4;
    float4 v0 = src[0], v1 = src[1], v2 = src[2], v3 = src[3];
    __half2 h[8];
    h[0] = __half2(__float2half_rn(v0.x), __float2half_rn(v0.y));
    h[1] = __half2(__float2half_rn(v0.z), __float2half_rn(v0.w));
    h[2] = __half2(__float2half_rn(v1.x), __float2half_rn(v1.y));
    h[3] = __half2(__float2half_rn(v1.z), __float2half_rn(v1.w));
    h[4] = __half2(__float2half_rn(v2.x), __float2half_rn(v2.y));
    h[5] = __half2(__float2half_rn(v2.z), __float2half_rn(v2.w));
    h[6] = __half2(__float2half_rn(v3.x), __float2half_rn(v3.y));
    h[7] = __half2(__float2half_rn(v3.z), __float2half_rn(v3.w));
    uint4* dst = (uint4*)(out + (size_t)idx * 16);
    dst[0] = *(uint4*)&h[0];
    dst[1] = *(uint4*)&h[4];
}

// QKV pack convert: in [1024,1024] per layer -> out rows of [1024,3072] at colofs.
__global__ __launch_bounds__(128) void convQ_k(const float* __restrict__ in,
                                               __half* __restrict__ out, int colofs){
    const long long DD = (long long)Dn * Dn;
    const float* pin = in + blockIdx.y * DD + (size_t)blockIdx.x * Dn;
    __half* pos = out + blockIdx.y * 3 * DD + (size_t)blockIdx.x * 3 * Dn + colofs;
    int c = threadIdx.x * 8;
    const float4* src = (const float4*)(pin + c);
    float4 v0 = src[0], v1 = src[1];
    __half2 h[4];
    h[0] = __half2(__float2half_rn(v0.x), __float2half_rn(v0.y));
    h[1] = __half2(__float2half_rn(v0.z), __float2half_rn(v0.w));
    h[2] = __half2(__float2half_rn(v1.x), __float2half_rn(v1.y));
    h[3] = __half2(__float2half_rn(v1.z), __float2half_rn(v1.w));
    *(uint4*)(pos + c) = *(uint4*)h;
}

// ==================== fused flash attention ====================
// grid (4 q-tiles, 64 bh), 256 threads (8 warps x 16 rows).
__global__ __launch_bounds__(256) void flash_k(
    const __half* __restrict__ q, const __half* __restrict__ k,
    const __half* __restrict__ v, __half* __restrict__ o)
{
    constexpr int PITCH = 144;                 // 64 halves + 16B pad
    constexpr int TILEB = 128 * PITCH;         // 18432
    extern __shared__ char sm[];
    const uint32_t smb = smem_u32(sm);
    const uint32_t Qs = smb, Ks = smb + TILEB, Vs = smb + 2 * TILEB;

    const int qt = blockIdx.x, bh = blockIdx.y;
    const int b = bh >> 4, h = bh & 15;
    const int tid = threadIdx.x, lane = tid & 31, w = tid >> 5;

    const __half* qbase = q + ((size_t)(b * Tn + qt * 128)) * Dn + h * HSn;
    const __half* kbase = k + ((size_t)(b * Tn)) * Dn + h * HSn;
    const __half* vbase = v + ((size_t)(b * Tn)) * Dn + h * HSn;

#pragma unroll
    for (int i = 0; i < 4; i++){
        int idx = i * 256 + tid;
        int r = idx >> 3, c = idx & 7;
        CP16(Qs + r * PITCH + c * 16, qbase + (size_t)r * Dn + c * 8);
    }
    CP_COMMIT();

    float m0 = -1e30f, m1 = -1e30f, l0 = 0.f, l1 = 0.f;
    float acc_o[8][4];
#pragma unroll
    for (int i = 0; i < 8; i++)
#pragma unroll
        for (int j = 0; j < 4; j++) acc_o[i][j] = 0.f;

    for (int kt = 0; kt <= qt; kt++){
        __syncthreads();
        const __half* kb = kbase + (size_t)(kt * 128) * Dn;
        const __half* vb = vbase + (size_t)(kt * 128) * Dn;
#pragma unroll
        for (int i = 0; i < 4; i++){
            int idx = i * 256 + tid;
            int r = idx >> 3, c = idx & 7;
            CP16(Ks + r * PITCH + c * 16, kb + (size_t)r * Dn + c * 8);
            CP16(Vs + r * PITCH + c * 16, vb + (size_t)r * Dn + c * 8);
        }
        CP_COMMIT();
        CP_WAIT0();
        __syncthreads();

        // ---- S = Q K^T (scale pre-folded into q) ----
        float acc_s[16][4];
#pragma unroll
        for (int i = 0; i < 16; i++)
#pragma unroll
            for (int j = 0; j < 4; j++) acc_s[i][j] = 0.f;

#pragma unroll
        for (int kc = 0; kc < 4; kc++){
            uint32_t a[4];
            {
                int row = w * 16 + (lane & 15);
                int colb = (kc * 16 + ((lane >> 4) << 3)) * 2;
                LDSM4(a[0], a[1], a[2], a[3], Qs + row * PITCH + colb);
            }
#pragma unroll
            for (int p = 0; p < 8; p++){
                int rowb = p * 16 + (lane & 7) + ((lane >> 4) << 3);
                int colb = (kc * 16 + (((lane >> 3) & 1) << 3)) * 2;
                uint32_t r0, r1, r2, r3;
                LDSM4(r0, r1, r2, r3, Ks + rowb * PITCH + colb);
                uint32_t b0[2] = {r0, r1}, b1[2] = {r2, r3};
                MMA16816(acc_s[2*p],   a, b0);
                MMA16816(acc_s[2*p+1], a, b1);
            }
        }

        // ---- causal mask (diagonal tile only) ----
        if (kt == qt){
            int r0g = w * 16 + (lane >> 2);
#pragma unroll
            for (int ni = 0; ni < 16; ni++){
#pragma unroll
                for (int c = 0; c < 4; c++){
                    int col = ni * 8 + (lane & 3) * 2 + (c & 1);
                    int row = r0g + ((c >> 1) << 3);
                    if (col > row) acc_s[ni][c] = -1e30f;
                }
            }
        }

        // ---- online softmax ----
        float mx0 = -1e30f, mx1 = -1e30f;
#pragma unroll
        for (int ni = 0; ni < 16; ni++){
            mx0 = fmaxf(mx0, fmaxf(acc_s[ni][0], acc_s[ni][1]));
            mx1 = fmaxf(mx1, fmaxf(acc_s[ni][2], acc_s[ni][3]));
        }
        mx0 = fmaxf(mx0, __shfl_xor_sync(0xffffffffu, mx0, 1));
        mx0 = fmaxf(mx0, __shfl_xor_sync(0xffffffffu, mx0, 2));
        mx1 = fmaxf(mx1, __shfl_xor_sync(0xffffffffu, mx1, 1));
        mx1 = fmaxf(mx1, __shfl_xor_sync(0xffffffffu, mx1, 2));
        float mn0 = fmaxf(m0, mx0), mn1 = fmaxf(m1, mx1);
        float rs0 = __expf(m0 - mn0), rs1 = __expf(m1 - mn1);
        m0 = mn0; m1 = mn1;

        float sum0 = 0.f, sum1 = 0.f;
#pragma unroll
        for (int ni = 0; ni < 16; ni++){
            float p0 = __expf(acc_s[ni][0] - mn0);
            float p1 = __expf(acc_s[ni][1] - mn0);
            float p2 = __expf(acc_s[ni][2] - mn1);
            float p3 = __expf(acc_s[ni][3] - mn1);
            sum0 += p0 + p1; sum1 += p2 + p3;
            acc_s[ni][0] = p0; acc_s[ni][1] = p1;
            acc_s[ni][2] = p2; acc_s[ni][3] = p3;
        }
        // FULL row sum: quad reduction (lanes hold disjoint columns)
        sum0 += __shfl_xor_sync(0xffffffffu, sum0, 1);
        sum0 += __shfl_xor_sync(0xffffffffu, sum0, 2);
        sum1 += __shfl_xor_sync(0xffffffffu, sum1, 1);
        sum1 += __shfl_xor_sync(0xffffffffu, sum1, 2);
        l0 = l0 * rs0 + sum0;
        l1 = l1 * rs1 + sum1;
#pragma unroll
        for (int ni = 0; ni < 8; ni++){
            acc_o[ni][0] *= rs0; acc_o[ni][1] *= rs0;
            acc_o[ni][2] *= rs1; acc_o[ni][3] *= rs1;
        }

        // ---- O += P V ----
#pragma unroll
        for (int j2 = 0; j2 < 8; j2++){
            uint32_t pa[4];
            {
                __half2 t0(__float2half_rn(acc_s[2*j2][0]),   __float2half_rn(acc_s[2*j2][1]));
                __half2 t1(__float2half_rn(acc_s[2*j2][2]),   __float2half_rn(acc_s[2*j2][3]));
                __half2 t2(__float2half_rn(acc_s[2*j2+1][0]), __float2half_rn(acc_s[2*j2+1][1]));
                __half2 t3(__float2half_rn(acc_s[2*j2+1][2]), __float2half_rn(acc_s[2*j2+1][3]));
                pa[0] = *(uint32_t*)&t0; pa[1] = *(uint32_t*)&t1;
                pa[2] = *(uint32_t*)&t2; pa[3] = *(uint32_t*)&t3;
            }
#pragma unroll
            for (int p = 0; p < 4; p++){
                int g = lane >> 3, rr = lane & 7;
                int row = j2 * 16 + (g & 1) * 8 + rr;
                int colb = (p * 16 + (g >> 1) * 8) * 2;
                uint32_t r0, r1, r2, r3;
                LDSM4T(r0, r1, r2, r3, Vs + row * PITCH + colb);
                uint32_t b0[2] = {r0, r1}, b1[2] = {r2, r3};
                MMA16816(acc_o[2*p],   pa, b0);
                MMA16816(acc_o[2*p+1], pa, b1);
            }
        }
    }

    // ---- epilogue ----
    float inv0 = 1.f / l0, inv1 = 1.f / l1;
    int row0 = qt * 128 + w * 16 + (lane >> 2);
    __half* ob = o + ((size_t)(b * Tn)) * Dn + h * HSn;
#pragma unroll
    for (int ni = 0; ni < 8; ni++){
        int col = ni * 8 + (lane & 3) * 2;
        __half2 v0(__float2half_rn(acc_o[ni][0] * inv0), __float2half_rn(acc_o[ni][1] * inv0));
        __half2 v1(__float2half_rn(acc_o[ni][2] * inv1), __float2half_rn(acc_o[ni][3] * inv1));
        *(__half2*)(ob + (size_t)row0 * Dn + col) = v0;
        *(__half2*)(ob + (size_t)(row0 + 8) * Dn + col) = v1;
    }
}

// ==================== fp16 mma.sync GEMM (3-stage pipeline, 1-pass) ========
#define F_BIAS   1
#define F_RES    2
#define F_RELU   4
#define F_QKV    64

template<int BN, bool BTRANS>
__global__ __launch_bounds__(256, 2) void gemm_mma(
    const __half* __restrict__ Ah,
    const __half* __restrict__ Bs,
    const float* __restrict__ bias, const float* __restrict__ res,
    float* __restrict__ Cf, __half* __restrict__ Ch,
    __half* __restrict__ C2, __half* __restrict__ C3,
    int K, int lda, int ldb, int ldc,
    int flags)
{
    constexpr int BM = 128, BK = 32;
    constexpr int ABYTES = BM * 40 * 2;
    constexpr int BPITCH = BTRANS ? (BN * 2 + 16) : 80;
    constexpr int BBYTES = BTRANS ? (BK * BPITCH) : (BN * 80);
    constexpr int STAGE = ABYTES + BBYTES;
    constexpr int WN = BN / 2;
    constexpr int NA = WN / 8;

    const int bm = blockIdx.y * BM, bn = blockIdx.x * BN;

    extern __shared__ char sm[];
    const uint32_t smb = smem_u32(sm);

    const int tid = threadIdx.x, lane = tid & 31, wid = tid >> 5;
    const int wm = wid & 3, wn = wid >> 2;

    const int nKB = K >> 5;

    auto loadStage = [&](int kb, int s){
        const int k0 = kb * BK;
        const uint32_t stg = smb + s * STAGE;
#pragma unroll
        for (int i = 0; i < 2; i++){
            int idx = i * 256 + tid;
            int r = idx >> 2, c = idx & 3;
            uint32_t dst = stg + r * 80 + c * 16;
            CP16(dst, Ah + (size_t)(bm + r) * lda + k0 + c * 8);
        }
        if (BTRANS){
            constexpr int CPR = BN / 8;
#pragma unroll
            for (int i = 0; i < (BK * CPR) / 256; i++){
                int idx = i * 256 + tid;
                int r = idx / CPR, c = idx % CPR;
                uint32_t dst = stg + ABYTES + r * BPITCH + c * 16;
                CP16(dst, Bs + (size_t)(k0 + r) * ldb + bn + c * 8);
            }
        } else {
#pragma unroll
            for (int i = 0; i < BN / 64; i++){
                int idx = i * 256 + tid;
                int r = idx >> 2, c = idx & 3;
                uint32_t dst = stg + ABYTES + r * 80 + c * 16;
                CP16(dst, Bs + (size_t)(bn + r) * ldb + k0 + c * 8);
            }
        }
        CP_COMMIT();
    };

    float acc[2][NA][4];
#pragma unroll
    for (int i = 0; i < 2; i++)
#pragma unroll
        for (int j = 0; j < NA; j++)
#pragma unroll
            for (int q = 0; q < 4; q++) acc[i][j][q] = 0.f;

    loadStage(0, 0);
    loadStage(1, 1);

    for (int kb = 0; kb < nKB; kb++){
        if (kb == nKB - 1) CP_WAIT0(); else CP_WAIT1();
        __syncthreads();
        if (kb + 2 < nKB){
            int s2 = kb + 2; while (s2 >= 3) s2 -= 3;
            loadStage(kb + 2, s2);
        }
        int s = kb; while (s >= 3) s -= 3;
        const uint32_t stg = smb + s * STAGE;
#pragma unroll
        for (int ks = 0; ks < 2; ks++){
            const int kc = ks * 16;
            uint32_t a_h[2][4];
#pragma unroll
            for (int mi = 0; mi < 2; mi++){
                int row = wm * 32 + mi * 16 + (lane & 15);
                int colb = (kc + ((lane >> 4) << 3)) * 2;
                uint32_t ad = stg + row * 80 + colb;
                LDSM4(a_h[mi][0], a_h[mi][1], a_h[mi][2], a_h[mi][3], ad);
            }
            uint32_t b_s[NA][2];
            if (BTRANS){
#pragma unroll
                for (int p = 0; p < NA / 2; p++){
                    int g = lane >> 3, rr = lane & 7;
                    int row = kc + (g & 1) * 8 + rr;
                    int colb = (wn * WN + p * 16 + (g >> 1) * 8) * 2;
                    uint32_t ad = stg + ABYTES + row * BPITCH + colb;
                    uint32_t r0, r1, r2, r3;
                    LDSM4T(r0, r1, r2, r3, ad);
                    b_s[2*p][0] = r0; b_s[2*p][1] = r1;
                    b_s[2*p+1][0] = r2; b_s[2*p+1][1] = r3;
                }
            } else {
#pragma unroll
                for (int p = 0; p < NA / 2; p++){
                    int rowb = wn * WN + p * 16 + (lane & 7) + ((lane >> 4) << 3);
                    int colb = (kc + (((lane >> 3) & 1) << 3)) * 2;
                    uint32_t ad = stg + ABYTES + rowb * 80 + colb;
                    uint32_t r0, r1, r2, r3;
                    LDSM4(r0, r1, r2, r3, ad);
                    b_s[2*p][0] = r0; b_s[2*p][1] = r1;
                    b_s[2*p+1][0] = r2; b_s[2*p+1][1] = r3;
                }
            }
#pragma unroll
            for (int mi = 0; mi < 2; mi++)
#pragma unroll
                for (int ni = 0; ni < NA; ni++)
                    MMA16816(acc[mi][ni], a_h[mi], b_s[ni]);
        }
    }

    // epilogue
#pragma unroll
    for (int mi = 0; mi < 2; mi++){
#pragma unroll
        for (int ni = 0; ni < NA; ni++){
            int r0 = bm + wm * 32 + mi * 16 + (lane >> 2);
            int c0 = bn + wn * WN + ni * 8 + (lane & 3) * 2;
#pragma unroll
            for (int half = 0; half < 2; half++){
                int r = r0 + half * 8;
                float vx = acc[mi][ni][half * 2 + 0];
                float vy = acc[mi][ni][half * 2 + 1];
                if (flags & F_QKV){
                    int range = c0 >> 10, cc = c0 & 1023;
                    if (range == 0){ vx *= 0.125f; vy *= 0.125f; }
                    __half2 hv(__float2half_rn(vx), __float2half_rn(vy));
                    if (range == 0)
                        *(__half2*)(Ch + (size_t)r * ldc + cc) = hv;
                    else if (range == 1)
                        *(__half2*)(C2 + (size_t)r * ldc + cc) = hv;
                    else
                        *(__half2*)(C3 + (size_t)r * ldc + cc) = hv;
                    continue;
                }
                if (flags & F_BIAS){ vx += bias[c0]; vy += bias[c0 + 1]; }
                if (flags & F_RES){
                    const float* rp = res + (size_t)r * ldc + c0;
                    vx += rp[0]; vy += rp[1];
                }
                if (flags & F_RELU){ vx = fmaxf(vx, 0.f); vy = fmaxf(vy, 0.f); }
                if (Cf){
                    float2 o2; o2.x = vx; o2.y = vy;
                    *(float2*)(Cf + (size_t)r * ldc + c0) = o2;
                }
                if (Ch){
                    __half2 hv(__float2half_rn(vx), __float2half_rn(vy));
                    *(__half2*)(Ch + (size_t)r * ldc + c0) = hv;
                }
            }
        }
    }
}

// ==================== host orchestration ====================
extern "C" void kernel_launch(void* const* d_in, const int* in_sizes, int n_in,
                              void* d_out, int out_size){
    (void)in_sizes; (void)n_in; (void)out_size;
    const int*   x     = (const int*)  d_in[0];
    const float* ce    = (const float*)d_in[1];
    const float* pe    = (const float*)d_in[2];
    const float* ln1_s = (const float*)d_in[5];
    const float* ln1_b = (const float*)d_in[6];
    const float* wq    = (const float*)d_in[7];
    const float* wk    = (const float*)d_in[8];
    const float* wv    = (const float*)d_in[9];
    const float* wo    = (const float*)d_in[10];
    const float* bo    = (const float*)d_in[11];
    const float* ln2_s = (const float*)d_in[12];
    const float* ln2_b = (const float*)d_in[13];
    const float* w1    = (const float*)d_in[14];
    const float* b1    = (const float*)d_in[15];
    const float* w2    = (const float*)d_in[16];
    const float* b2    = (const float*)d_in[17];
    const float* lnf_s = (const float*)d_in[18];
    const float* lnf_b = (const float*)d_in[19];
    const float* wf    = (const float*)d_in[20];
    const float* bf    = (const float*)d_in[21];

    float *h;
    cudaGetSymbolAddress((void**)&h, g_h);

    __half *yS,*qS,*kS,*vS,*oS,*aS;
    cudaGetSymbolAddress((void**)&yS, g_yS);
    cudaGetSymbolAddress((void**)&qS, g_qS);
    cudaGetSymbolAddress((void**)&kS, g_kS);
    cudaGetSymbolAddress((void**)&vS, g_vS);
    cudaGetSymbolAddress((void**)&oS, g_oS);
    cudaGetSymbolAddress((void**)&aS, g_aS);

    __half *wqkvS,*woS,*w1S,*w2S,*wfS;
    cudaGetSymbolAddress((void**)&wqkvS, g_wqkvS);
    cudaGetSymbolAddress((void**)&woS, g_woS);
    cudaGetSymbolAddress((void**)&w1S, g_w1S);
    cudaGetSymbolAddress((void**)&w2S, g_w2S);
    cudaGetSymbolAddress((void**)&wfS, g_wfS);

    const int SMWT = 56832, SMFL = 55296;
    cudaFuncSetAttribute((const void*)gemm_mma<128,true>, cudaFuncAttributeMaxDynamicSharedMemorySize, SMWT);
    cudaFuncSetAttribute((const void*)flash_k,            cudaFuncAttributeMaxDynamicSharedMemorySize, SMFL);

    // streams: s1 = compute (HIGH priority), s2 = weight converts (LOW priority)
    static cudaStream_t s1 = nullptr, s2 = nullptr;
    static cudaEvent_t evF = nullptr, evL[Ln], evWf = nullptr, evEnd = nullptr;
    if (!s1){
        int lo, hi;
        cudaDeviceGetStreamPriorityRange(&lo, &hi);   // hi = numerically smallest = highest
        cudaStreamCreateWithPriority(&s1, cudaStreamNonBlocking, hi);
        cudaStreamCreateWithPriority(&s2, cudaStreamNonBlocking, lo);
        cudaEventCreateWithFlags(&evF, cudaEventDisableTiming);
        for (int l = 0; l < Ln; l++) cudaEventCreateWithFlags(&evL[l], cudaEventDisableTiming);
        cudaEventCreateWithFlags(&evWf, cudaEventDisableTiming);
        cudaEventCreateWithFlags(&evEnd, cudaEventDisableTiming);
    }

    const long long DD = (long long)Dn * Dn;
    const long long DF = (long long)Dn * FFn;

    // ---- fork from captured stream into s1 (compute) and s2 (converts)
    cudaEventRecord(evF, 0);
    cudaStreamWaitEvent(s1, evF, 0);
    cudaStreamWaitEvent(s2, evF, 0);

    // ---- s2 (low priority): per-layer weight converts for layers 1..7, then wf
    for (int l = 1; l < Ln; l++){
        convQ_k<<<dim3(Dn, 1), 128, 0, s2>>>(wq + (size_t)l*DD, wqkvS + (size_t)l*3*DD, 0);
        convQ_k<<<dim3(Dn, 1), 128, 0, s2>>>(wk + (size_t)l*DD, wqkvS + (size_t)l*3*DD, Dn);
        convQ_k<<<dim3(Dn, 1), 128, 0, s2>>>(wv + (size_t)l*DD, wqkvS + (size_t)l*3*DD, 2*Dn);
        convF_k<<<(int)(DD/16/256), 256, 0, s2>>>(wo + (size_t)l*DD, woS + (size_t)l*DD, (int)(DD/16));
        convF_k<<<(int)(DF/16/256), 256, 0, s2>>>(w1 + (size_t)l*DF, w1S + (size_t)l*DF, (int)(DF/16));
        convF_k<<<(int)(DF/16/256), 256, 0, s2>>>(w2 + (size_t)l*DF, w2S + (size_t)l*DF, (int)(DF/16));
        cudaEventRecord(evL[l], s2);
    }
    convF_k<<<(int)(((long long)Dn*Vn/16) + 255)/256, 256, 0, s2>>>(wf, wfS, (int)((long long)Dn*Vn/16));
    cudaEventRecord(evWf, s2);

    // ---- s1 (high priority): layer-0 converts, then the compute chain
    convQ_k<<<dim3(Dn, 1), 128, 0, s1>>>(wq, wqkvS, 0);
    convQ_k<<<dim3(Dn, 1), 128, 0, s1>>>(wk, wqkvS, Dn);
    convQ_k<<<dim3(Dn, 1), 128, 0, s1>>>(wv, wqkvS, 2*Dn);
    convF_k<<<(int)(DD/16/256), 256, 0, s1>>>(wo, woS, (int)(DD/16));
    convF_k<<<(int)(DF/16/256), 256, 0, s1>>>(w1, w1S, (int)(DF/16));
    convF_k<<<(int)(DF/16/256), 256, 0, s1>>>(w2, w2S, (int)(DF/16));

    embed_k<<<(Mn * Dn) / 256, 256, 0, s1>>>(x, ce, pe);

    for (int l = 0; l < Ln; l++){
        if (l >= 1) cudaStreamWaitEvent(s1, evL[l], 0);   // layer-l weights ready

        ln_k<<<Mn, 256, 0, s1>>>(h, yS, ln1_s + l*Dn, ln1_b + l*Dn);

        gemm_mma<128,true><<<dim3(24,16,1), 256, SMWT, s1>>>(yS,
            wqkvS + (size_t)l*3*DD,
            nullptr, nullptr, nullptr, qS, kS, vS, Dn, Dn, 3*Dn, Dn, F_QKV);

        flash_k<<<dim3(4, BHn), 256, SMFL, s1>>>(qS, kS, vS, oS);

        gemm_mma<128,true><<<dim3(8,16,1), 256, SMWT, s1>>>(oS,
            woS + (size_t)l*DD,
            bo + l*Dn, h, h, nullptr, nullptr, nullptr, Dn, Dn, Dn, Dn,
            F_BIAS | F_RES);

        ln_k<<<Mn, 256, 0, s1>>>(h, yS, ln2_s + l*Dn, ln2_b + l*Dn);

        gemm_mma<128,true><<<dim3(32,16,1), 256, SMWT, s1>>>(yS,
            w1S + (size_t)l*DF,
            b1 + l*FFn, nullptr, nullptr, aS, nullptr, nullptr,
            Dn, Dn, FFn, FFn, F_BIAS | F_RELU);

        gemm_mma<128,true><<<dim3(8,16,1), 256, SMWT, s1>>>(aS,
            w2S + (size_t)l*DF,
            b2 + l*Dn, h, h, nullptr, nullptr, nullptr,
            FFn, FFn, Dn, Dn, F_BIAS | F_RES);
    }

    ln_k<<<Mn, 256, 0, s1>>>(h, yS, lnf_s, lnf_b);

    cudaStreamWaitEvent(s1, evWf, 0);   // wf ready (also merges s2 branch)
    gemm_mma<128,true><<<dim3(Vn/128, 16, 1), 256, SMWT, s1>>>(yS, wfS,
        bf, nullptr, (float*)d_out, nullptr, nullptr, nullptr,
        Dn, Dn, Vn, Vn, F_BIAS);

    // ---- join back into the captured stream
    cudaEventRecord(evEnd, s1);
    cudaStreamWaitEvent(0, evEnd, 0);
}